// round 7
// baseline (speedup 1.0000x reference)
#include <cuda_runtime.h>

// ThoughtEngine: B=8, L=1024, D=1024, H=16, HD=64, S=32, C=8. fp32.
// R6: persistent loop kernel (grid-barrier) + FFMA2 (fma.rn.f32x2) GEMM.

#define LL (size_t)

static const size_t OFF_QKVH = 0;                              // 8192*3072
static const size_t OFF_BUF  = OFF_QKVH + LL 8192 * 3072;      // 8*32*1024
static const size_t OFF_KVB  = OFF_BUF  + LL 8 * 32 * 1024;    // 8*32*2048
static const size_t OFF_CTX  = OFF_KVB  + LL 8 * 32 * 2048;
static const size_t OFF_TOK  = OFF_CTX + 8192;
static const size_t OFF_TMP  = OFF_TOK + 8192;
static const size_t OFF_H1   = OFF_TMP + 8192;                 // 8*2048
static const size_t OFF_Q    = OFF_H1 + 16384;
static const size_t OFF_AO   = OFF_Q + 8192;
static const size_t OFF_KVS  = OFF_AO + 8192;                  // 64*2048
static const size_t OFF_SSUM = OFF_KVS + 131072;               // 64*1024
static const size_t OFF_O    = OFF_SSUM + 65536;               // 8192*1024
static const size_t OFF_ATT  = OFF_O + LL 8192 * 1024;         // 8192*1024
static const size_t SCR_TOT  = OFF_ATT + LL 8192 * 1024;

__device__ __align__(16) float g_scratch[SCR_TOT];
__device__ unsigned g_bar = 0;   // monotonic ticket counter (wrap-safe: 2^32 % 128 == 0)

__device__ __forceinline__ float geluf(float x) {
    return 0.5f * x * (1.0f + erff(x * 0.7071067811865475f));
}

// Grid barrier over exactly 128 resident blocks. Monotonic counter, no reset.
__device__ __forceinline__ void grid_sync() {
    __syncthreads();
    if (threadIdx.x == 0) {
        __threadfence();
        unsigned t = atomicAdd(&g_bar, 1u);
        unsigned target = (t & ~127u) + 128u;
        while ((int)(*(volatile unsigned*)&g_bar - target) < 0) { }
        __threadfence();
    }
    __syncthreads();
}

// ctx[b,d] = mean_l hidden[b,l,d]
__global__ void mean_kernel(const float* __restrict__ hidden, float* __restrict__ ctx) {
    int b = blockIdx.y;
    int d = blockIdx.x * 256 + threadIdx.x;
    const float* p = hidden + LL b * 1048576 + d;
    float s = 0.f;
    #pragma unroll 8
    for (int l = 0; l < 1024; ++l) s += p[LL l * 1024];
    ctx[b * 1024 + d] = s * (1.0f / 1024.0f);
}

__global__ void copy_to_buf(const float* __restrict__ tok, float* __restrict__ buf, int slot) {
    int b = blockIdx.x;
    int d = blockIdx.y * 256 + threadIdx.x;
    buf[LL(b * 32 + slot) * 1024 + d] = tok[b * 1024 + d];
}

// ============================================================================
// FFMA2 GEMM: C[M,N] = A[M,K] @ B[N,K]^T + bias. BM=128 BN=64 BK=16, 256 thr.
// A stored DUPLICATED in smem so ld.shared.b64 yields packed (a,a); B pairs
// are natural. 16 fma.rn.f32x2 per k per thread (vs 32 bank-limited FFMA).
// ============================================================================
__global__ __launch_bounds__(256) void sgemm2(
    const float* __restrict__ A, const float* __restrict__ B,
    const float* __restrict__ bias, float* __restrict__ C,
    int M, int N, int K)
{
    __shared__ __align__(16) float As2[16][256];   // [k][2m],[2m+1] duplicated
    __shared__ __align__(16) float Bs[16][64];
    int tid = threadIdx.x;
    int tx = tid & 15, ty = tid >> 4;
    int bm = blockIdx.y * 128, bn = blockIdx.x * 64;
    unsigned long long acc2[8][2];
    #pragma unroll
    for (int i = 0; i < 8; ++i) { acc2[i][0] = 0ull; acc2[i][1] = 0ull; }

    for (int kk = 0; kk < K; kk += 16) {
        #pragma unroll
        for (int s = tid; s < 512; s += 256) {     // A: 128 rows x 4 float4
            int r = s >> 2, c = (s & 3) << 2;
            int gr = bm + r;
            float4 v = make_float4(0.f, 0.f, 0.f, 0.f);
            if (gr < M) v = *reinterpret_cast<const float4*>(A + LL gr * K + kk + c);
            As2[c][2 * r] = v.x;     As2[c][2 * r + 1] = v.x;
            As2[c + 1][2 * r] = v.y; As2[c + 1][2 * r + 1] = v.y;
            As2[c + 2][2 * r] = v.z; As2[c + 2][2 * r + 1] = v.z;
            As2[c + 3][2 * r] = v.w; As2[c + 3][2 * r + 1] = v.w;
        }
        {
            int r = tid >> 2, c = (tid & 3) << 2;  // B: 64 rows x 4 float4
            float4 v = *reinterpret_cast<const float4*>(B + LL(bn + r) * K + kk + c);
            Bs[c][r] = v.x; Bs[c + 1][r] = v.y; Bs[c + 2][r] = v.z; Bs[c + 3][r] = v.w;
        }
        __syncthreads();
        #pragma unroll
        for (int k = 0; k < 16; ++k) {
            unsigned long long a2[8], b2[2];
            const unsigned long long* ap =
                reinterpret_cast<const unsigned long long*>(&As2[k][0]) + ty * 8;
            #pragma unroll
            for (int i = 0; i < 8; ++i) a2[i] = ap[i];
            const unsigned long long* bp =
                reinterpret_cast<const unsigned long long*>(&Bs[k][0]) + tx * 2;
            b2[0] = bp[0]; b2[1] = bp[1];
            #pragma unroll
            for (int i = 0; i < 8; ++i) {
                asm("fma.rn.f32x2 %0, %1, %2, %0;" : "+l"(acc2[i][0]) : "l"(a2[i]), "l"(b2[0]));
                asm("fma.rn.f32x2 %0, %1, %2, %0;" : "+l"(acc2[i][1]) : "l"(a2[i]), "l"(b2[1]));
            }
        }
        __syncthreads();
    }
    #pragma unroll
    for (int i = 0; i < 8; ++i) {
        int row = bm + ty * 8 + i;
        if (row < M) {
            float* cr = C + LL row * N + bn + tx * 4;
            #pragma unroll
            for (int jp = 0; jp < 2; ++jp) {
                unsigned long long v = acc2[i][jp];
                float lo = __uint_as_float((unsigned)v);
                float hi = __uint_as_float((unsigned)(v >> 32));
                cr[2 * jp]     = lo + bias[bn + tx * 4 + 2 * jp];
                cr[2 * jp + 1] = hi + bias[bn + tx * 4 + 2 * jp + 1];
            }
        }
    }
}

// out[b,n] = A[b,:K].W[n,:K] + bias[n], 8 rows, warp per n (Phase A tok0 only).
__global__ __launch_bounds__(256) void smallgemm8(
    const float* __restrict__ A, int K,
    const float* __restrict__ W, const float* __restrict__ bias,
    float* __restrict__ out, int N)
{
    __shared__ __align__(16) float As[8 * 1024];
    int tid = threadIdx.x, lane = tid & 31, w = tid >> 5;
    int n = blockIdx.x * 8 + w;
    float acc[8];
    #pragma unroll
    for (int b = 0; b < 8; ++b) acc[b] = 0.f;
    for (int kk = 0; kk < K; kk += 1024) {
        for (int i = tid; i < 8192; i += 256) {
            int b = i >> 10, k = i & 1023;
            As[i] = A[LL b * K + kk + k];
        }
        __syncthreads();
        const float4* wr = reinterpret_cast<const float4*>(W + LL n * K + kk);
        for (int k4 = lane; k4 < 256; k4 += 32) {
            float4 wv = wr[k4];
            #pragma unroll
            for (int b = 0; b < 8; ++b) {
                float4 av = reinterpret_cast<const float4*>(As + b * 1024)[k4];
                acc[b] += wv.x * av.x + wv.y * av.y + wv.z * av.z + wv.w * av.w;
            }
        }
        __syncthreads();
    }
    #pragma unroll
    for (int off = 16; off; off >>= 1)
        #pragma unroll
        for (int b = 0; b < 8; ++b) acc[b] += __shfl_down_sync(0xffffffffu, acc[b], off);
    if (lane == 0) {
        float bv = bias[n];
        #pragma unroll
        for (int b = 0; b < 8; ++b) out[b * N + n] = acc[b] + bv;
    }
}

// ============================================================================
// Persistent kernel: runs all 31 sequential steps with grid barriers.
// 128 blocks x 256 threads, all resident. Mutable cross-barrier buffers are
// read with __ldcg (L1 incoherent across SMs); read-only (weights, QKVH) and
// write-once (KVB after its barrier) data uses normal cached loads.
// ============================================================================
__global__ __launch_bounds__(256) void loop_kernel(
    const float* __restrict__ aiw, const float* __restrict__ aib,
    const float* __restrict__ aow, const float* __restrict__ aob,
    const float* __restrict__ fw1, const float* __restrict__ fb1,
    const float* __restrict__ fw2, const float* __restrict__ fb2,
    const float* __restrict__ ln1g, const float* __restrict__ ln1b,
    const float* __restrict__ ln2g, const float* __restrict__ ln2b,
    const float* __restrict__ qkvh,
    float* tok, float* q, float* kvb, float* ao, float* tmp, float* h1,
    float* buf)
{
    __shared__ __align__(16) float sA[8192];   // 32KB staging
    __shared__ float sc[1056];
    __shared__ float red[256];
    __shared__ float part[4][64];
    int tid = threadIdx.x, lane = tid & 31, w = tid >> 5;
    int bid = blockIdx.x;

    for (int i = 1; i < 32; ++i) {
        // ---- S1: qkv of tok -> q (n<1024) and kvb slot i-1 (n>=1024) ----
        for (int idx = tid; idx < 8192; idx += 256) sA[idx] = __ldcg(tok + idx);
        __syncthreads();
        for (int n = bid * 8 + w; n < 3072; n += 1024) {
            const float4* wr = reinterpret_cast<const float4*>(aiw + LL n * 1024);
            float acc[8];
            #pragma unroll
            for (int b = 0; b < 8; ++b) acc[b] = 0.f;
            for (int k4 = lane; k4 < 256; k4 += 32) {
                float4 wv = wr[k4];
                #pragma unroll
                for (int b = 0; b < 8; ++b) {
                    float4 av = reinterpret_cast<const float4*>(sA + b * 1024)[k4];
                    acc[b] += wv.x * av.x + wv.y * av.y + wv.z * av.z + wv.w * av.w;
                }
            }
            #pragma unroll
            for (int off = 16; off; off >>= 1)
                #pragma unroll
                for (int b = 0; b < 8; ++b) acc[b] += __shfl_down_sync(0xffffffffu, acc[b], off);
            if (lane == 0) {
                float bv = aib[n];
                #pragma unroll
                for (int b = 0; b < 8; ++b) {
                    float v = acc[b] + bv;
                    if (n < 1024) q[b * 1024 + n] = v;
                    else kvb[LL(b * 32 + i - 1) * 2048 + (n - 1024)] = v;
                }
            }
        }
        grid_sync();

        // ---- S2: attention over 1024+i keys, block = (b,h) ----
        if (bid < 128) {
            int b = bid >> 4, h = bid & 15;
            int Lk = 1024 + i;
            if (tid < 64) sA[tid] = __ldcg(q + b * 1024 + h * 64 + tid);
            __syncthreads();
            float lmax = -1e30f;
            for (int j = tid; j < Lk; j += 256) {
                float s = 0.f;
                if (j < 1024) {
                    const float4* k4 = reinterpret_cast<const float4*>(
                        qkvh + LL(b * 1024 + j) * 3072 + 1024 + h * 64);
                    const float4* q4 = reinterpret_cast<const float4*>(sA);
                    #pragma unroll
                    for (int d = 0; d < 16; ++d) {
                        float4 kv = k4[d], qv = q4[d];
                        s += kv.x * qv.x + kv.y * qv.y + kv.z * qv.z + kv.w * qv.w;
                    }
                } else {
                    const float* kr = kvb + LL(b * 32 + j - 1024) * 2048 + h * 64;
                    #pragma unroll
                    for (int d = 0; d < 64; ++d) s += __ldcg(kr + d) * sA[d];
                }
                s *= 0.125f;
                sc[j] = s;
                lmax = fmaxf(lmax, s);
            }
            red[tid] = lmax; __syncthreads();
            for (int o = 128; o; o >>= 1) { if (tid < o) red[tid] = fmaxf(red[tid], red[tid + o]); __syncthreads(); }
            float m = red[0];
            __syncthreads();
            float lsum = 0.f;
            for (int j = tid; j < Lk; j += 256) { float p = __expf(sc[j] - m); sc[j] = p; lsum += p; }
            red[tid] = lsum; __syncthreads();
            for (int o = 128; o; o >>= 1) { if (tid < o) red[tid] += red[tid + o]; __syncthreads(); }
            float inv = 1.0f / red[0];
            int d = tid & 63, g = tid >> 6;
            float acc = 0.f;
            for (int j = g; j < Lk; j += 4) {
                float vv = (j < 1024)
                    ? qkvh[LL(b * 1024 + j) * 3072 + 2048 + h * 64 + d]
                    : __ldcg(kvb + LL(b * 32 + j - 1024) * 2048 + 1024 + h * 64 + d);
                acc += sc[j] * vv;
            }
            part[g][d] = acc; __syncthreads();
            if (tid < 64)
                ao[b * 1024 + h * 64 + tid] =
                    (part[0][tid] + part[1][tid] + part[2][tid] + part[3][tid]) * inv;
        }
        grid_sync();

        // ---- S3: out-proj + residual -> tmp ----
        for (int idx = tid; idx < 8192; idx += 256) sA[idx] = __ldcg(ao + idx);
        __syncthreads();
        {
            int n = bid * 8 + w;   // exactly 1024 warps
            const float4* wr = reinterpret_cast<const float4*>(aow + LL n * 1024);
            float acc[8];
            #pragma unroll
            for (int b = 0; b < 8; ++b) acc[b] = 0.f;
            for (int k4 = lane; k4 < 256; k4 += 32) {
                float4 wv = wr[k4];
                #pragma unroll
                for (int b = 0; b < 8; ++b) {
                    float4 av = reinterpret_cast<const float4*>(sA + b * 1024)[k4];
                    acc[b] += wv.x * av.x + wv.y * av.y + wv.z * av.z + wv.w * av.w;
                }
            }
            #pragma unroll
            for (int off = 16; off; off >>= 1)
                #pragma unroll
                for (int b = 0; b < 8; ++b) acc[b] += __shfl_down_sync(0xffffffffu, acc[b], off);
            if (lane == 0) {
                float bv = aob[n];
                #pragma unroll
                for (int b = 0; b < 8; ++b)
                    tmp[b * 1024 + n] = acc[b] + bv + __ldcg(tok + b * 1024 + n);
            }
        }
        grid_sync();

        // ---- S4: LN1 -> tok ----
        if (bid < 8) {
            int b = bid;
            float vals[4]; float s = 0.f;
            #pragma unroll
            for (int u = 0; u < 4; ++u) { vals[u] = __ldcg(tmp + b * 1024 + tid + 256 * u); s += vals[u]; }
            red[tid] = s; __syncthreads();
            for (int o = 128; o; o >>= 1) { if (tid < o) red[tid] += red[tid + o]; __syncthreads(); }
            float mean = red[0] * (1.0f / 1024.0f);
            __syncthreads();
            float v = 0.f;
            #pragma unroll
            for (int u = 0; u < 4; ++u) { float dd = vals[u] - mean; v += dd * dd; }
            red[tid] = v; __syncthreads();
            for (int o = 128; o; o >>= 1) { if (tid < o) red[tid] += red[tid + o]; __syncthreads(); }
            float inv = rsqrtf(red[0] * (1.0f / 1024.0f) + 1e-5f);
            #pragma unroll
            for (int u = 0; u < 4; ++u) {
                int d = tid + 256 * u;
                tok[b * 1024 + d] = (vals[u] - mean) * inv * ln1g[d] + ln1b[d];
            }
        }
        grid_sync();

        // ---- S5: FFN1 + gelu -> h1 ----
        for (int idx = tid; idx < 8192; idx += 256) sA[idx] = __ldcg(tok + idx);
        __syncthreads();
        for (int n = bid * 8 + w; n < 2048; n += 1024) {
            const float4* wr = reinterpret_cast<const float4*>(fw1 + LL n * 1024);
            float acc[8];
            #pragma unroll
            for (int b = 0; b < 8; ++b) acc[b] = 0.f;
            for (int k4 = lane; k4 < 256; k4 += 32) {
                float4 wv = wr[k4];
                #pragma unroll
                for (int b = 0; b < 8; ++b) {
                    float4 av = reinterpret_cast<const float4*>(sA + b * 1024)[k4];
                    acc[b] += wv.x * av.x + wv.y * av.y + wv.z * av.z + wv.w * av.w;
                }
            }
            #pragma unroll
            for (int off = 16; off; off >>= 1)
                #pragma unroll
                for (int b = 0; b < 8; ++b) acc[b] += __shfl_down_sync(0xffffffffu, acc[b], off);
            if (lane == 0) {
                float bv = fb1[n];
                #pragma unroll
                for (int b = 0; b < 8; ++b) h1[b * 2048 + n] = geluf(acc[b] + bv);
            }
        }
        grid_sync();

        // ---- S6: FFN2 + residual -> tmp ----
        {
            float acc[8];
            #pragma unroll
            for (int b = 0; b < 8; ++b) acc[b] = 0.f;
            int n = bid * 8 + w;
            for (int kk = 0; kk < 2048; kk += 1024) {
                for (int idx = tid; idx < 8192; idx += 256) {
                    int b = idx >> 10, k = idx & 1023;
                    sA[idx] = __ldcg(h1 + b * 2048 + kk + k);
                }
                __syncthreads();
                const float4* wr = reinterpret_cast<const float4*>(fw2 + LL n * 2048 + kk);
                for (int k4 = lane; k4 < 256; k4 += 32) {
                    float4 wv = wr[k4];
                    #pragma unroll
                    for (int b = 0; b < 8; ++b) {
                        float4 av = reinterpret_cast<const float4*>(sA + b * 1024)[k4];
                        acc[b] += wv.x * av.x + wv.y * av.y + wv.z * av.z + wv.w * av.w;
                    }
                }
                __syncthreads();
            }
            #pragma unroll
            for (int off = 16; off; off >>= 1)
                #pragma unroll
                for (int b = 0; b < 8; ++b) acc[b] += __shfl_down_sync(0xffffffffu, acc[b], off);
            if (lane == 0) {
                float bv = fb2[n];
                #pragma unroll
                for (int b = 0; b < 8; ++b)
                    tmp[b * 1024 + n] = acc[b] + bv + __ldcg(tok + b * 1024 + n);
            }
        }
        grid_sync();

        // ---- S7: LN2 -> tok and buf[:, i] ----
        if (bid < 8) {
            int b = bid;
            float vals[4]; float s = 0.f;
            #pragma unroll
            for (int u = 0; u < 4; ++u) { vals[u] = __ldcg(tmp + b * 1024 + tid + 256 * u); s += vals[u]; }
            red[tid] = s; __syncthreads();
            for (int o = 128; o; o >>= 1) { if (tid < o) red[tid] += red[tid + o]; __syncthreads(); }
            float mean = red[0] * (1.0f / 1024.0f);
            __syncthreads();
            float v = 0.f;
            #pragma unroll
            for (int u = 0; u < 4; ++u) { float dd = vals[u] - mean; v += dd * dd; }
            red[tid] = v; __syncthreads();
            for (int o = 128; o; o >>= 1) { if (tid < o) red[tid] += red[tid + o]; __syncthreads(); }
            float inv = rsqrtf(red[0] * (1.0f / 1024.0f) + 1e-5f);
            #pragma unroll
            for (int u = 0; u < 4; ++u) {
                int d = tid + 256 * u;
                float y = (vals[u] - mean) * inv * ln2g[d] + ln2b[d];
                tok[b * 1024 + d] = y;
                buf[LL(b * 32 + i) * 1024 + d] = y;
            }
        }
        grid_sync();
    }
}

// cond[l] = LN(hidden[l] + att[l])
__global__ void ln_big(const float* __restrict__ hidden, const float* __restrict__ att,
                       const float* __restrict__ gg, const float* __restrict__ bb,
                       float* __restrict__ out)
{
    int l = blockIdx.x, tid = threadIdx.x;
    __shared__ float red[256];
    const float* hr = hidden + LL l * 1024;
    const float* ar = att + LL l * 1024;
    float vals[4]; float s = 0.f;
    #pragma unroll
    for (int i = 0; i < 4; ++i) { vals[i] = hr[tid + 256 * i] + ar[tid + 256 * i]; s += vals[i]; }
    red[tid] = s; __syncthreads();
    for (int o = 128; o; o >>= 1) { if (tid < o) red[tid] += red[tid + o]; __syncthreads(); }
    float mean = red[0] * (1.0f / 1024.0f);
    __syncthreads();
    float v = 0.f;
    #pragma unroll
    for (int i = 0; i < 4; ++i) { float dd = vals[i] - mean; v += dd * dd; }
    red[tid] = v; __syncthreads();
    for (int o = 128; o; o >>= 1) { if (tid < o) red[tid] += red[tid + o]; __syncthreads(); }
    float inv = rsqrtf(red[0] * (1.0f / 1024.0f) + 1e-5f);
    #pragma unroll
    for (int i = 0; i < 4; ++i) {
        int d = tid + 256 * i;
        out[LL l * 1024 + d] = (vals[i] - mean) * inv * gg[d] + bb[d];
    }
}

// ssum[b,c,:] = softmax_s(comp_q[c].thoughts[b,s] / 32) @ thoughts[b]
__global__ __launch_bounds__(256) void comp_kernel(
    const float* __restrict__ comp_q, const float* __restrict__ thoughts,
    float* __restrict__ ssum)
{
    int b = blockIdx.x >> 3, c = blockIdx.x & 7;
    __shared__ float sc[32];
    __shared__ float pr[32];
    int tid = threadIdx.x, lane = tid & 31, w = tid >> 5;
    const float* qr = comp_q + c * 1024;
    #pragma unroll
    for (int si = 0; si < 4; ++si) {
        int s = w * 4 + si;
        const float* t = thoughts + LL(b * 32 + s) * 1024;
        float acc = 0.f;
        for (int k = lane; k < 1024; k += 32) acc += qr[k] * t[k];
        #pragma unroll
        for (int o = 16; o; o >>= 1) acc += __shfl_down_sync(0xffffffffu, acc, o);
        if (lane == 0) sc[s] = acc * (1.0f / 32.0f);
    }
    __syncthreads();
    if (tid == 0) {
        float m = -1e30f;
        for (int s = 0; s < 32; ++s) m = fmaxf(m, sc[s]);
        float S = 0.f;
        for (int s = 0; s < 32; ++s) { float p = __expf(sc[s] - m); pr[s] = p; S += p; }
        float iv = 1.0f / S;
        for (int s = 0; s < 32; ++s) pr[s] *= iv;
    }
    __syncthreads();
    for (int d = tid; d < 1024; d += 256) {
        float acc = 0.f;
        #pragma unroll
        for (int s = 0; s < 32; ++s) acc += pr[s] * thoughts[LL(b * 32 + s) * 1024 + d];
        ssum[LL(b * 8 + c) * 1024 + d] = acc;
    }
}

// Final MHA: one warp per (row l, head h); 8 keys from kvs (k|v rows).
__global__ __launch_bounds__(256) void final_attn(
    const float* __restrict__ qkvh, const float* __restrict__ kvs,
    float* __restrict__ o)
{
    int tid = threadIdx.x, lane = tid & 31, w = tid >> 5;
    int pair = blockIdx.x * 8 + w;
    int l = pair >> 4, h = pair & 15;
    int b = l >> 10;
    float2 qv = reinterpret_cast<const float2*>(qkvh + LL l * 3072 + h * 64)[lane];
    float s[8];
    #pragma unroll
    for (int ks = 0; ks < 8; ++ks) {
        float2 kv = reinterpret_cast<const float2*>(kvs + LL(b * 8 + ks) * 2048 + h * 64)[lane];
        float p = qv.x * kv.x + qv.y * kv.y;
        #pragma unroll
        for (int off = 16; off; off >>= 1) p += __shfl_xor_sync(0xffffffffu, p, off);
        s[ks] = p * 0.125f;
    }
    float m = s[0];
    #pragma unroll
    for (int ks = 1; ks < 8; ++ks) m = fmaxf(m, s[ks]);
    float sum = 0.f;
    #pragma unroll
    for (int ks = 0; ks < 8; ++ks) { s[ks] = __expf(s[ks] - m); sum += s[ks]; }
    float inv = 1.0f / sum;
    float o0 = 0.f, o1 = 0.f;
    #pragma unroll
    for (int ks = 0; ks < 8; ++ks) {
        float2 vv = reinterpret_cast<const float2*>(kvs + LL(b * 8 + ks) * 2048 + 1024 + h * 64)[lane];
        o0 += s[ks] * vv.x; o1 += s[ks] * vv.y;
    }
    float2 ov; ov.x = o0 * inv; ov.y = o1 * inv;
    reinterpret_cast<float2*>(o + LL l * 1024 + h * 64)[lane] = ov;
}

extern "C" void kernel_launch(void* const* d_in, const int* in_sizes, int n_in,
                              void* d_out, int out_size) {
    (void)in_sizes; (void)n_in; (void)out_size;
    const float* hidden = (const float*)d_in[0];
    const float* tpw    = (const float*)d_in[1];
    const float* tpb    = (const float*)d_in[2];
    const float* ln1g   = (const float*)d_in[3];
    const float* ln1b   = (const float*)d_in[4];
    const float* ln2g   = (const float*)d_in[5];
    const float* ln2b   = (const float*)d_in[6];
    const float* aiw    = (const float*)d_in[7];
    const float* aib    = (const float*)d_in[8];
    const float* aow    = (const float*)d_in[9];
    const float* aob    = (const float*)d_in[10];
    const float* fw1    = (const float*)d_in[11];
    const float* fb1    = (const float*)d_in[12];
    const float* fw2    = (const float*)d_in[13];
    const float* fb2    = (const float*)d_in[14];
    const float* cq     = (const float*)d_in[15];
    const float* cw     = (const float*)d_in[16];
    const float* cb     = (const float*)d_in[17];
    float* out = (float*)d_out;

    float* S;
    cudaGetSymbolAddress((void**)&S, g_scratch);
    float* QKVH = S + OFF_QKVH;
    float* BUF  = S + OFF_BUF;
    float* KVB  = S + OFF_KVB;
    float* CTX  = S + OFF_CTX;
    float* TOK  = S + OFF_TOK;
    float* TMP  = S + OFF_TMP;
    float* H1   = S + OFF_H1;
    float* Q    = S + OFF_Q;
    float* AO   = S + OFF_AO;
    float* KVS  = S + OFF_KVS;
    float* SSUM = S + OFF_SSUM;
    float* O    = S + OFF_O;
    float* ATT  = S + OFF_ATT;
    float* SUMM = out + LL 8192 * 1024;   // (8,8,1024) tail of output

    // Phase A
    mean_kernel<<<dim3(4, 8), 256>>>(hidden, CTX);
    smallgemm8<<<128, 256>>>(CTX, 1024, tpw, tpb, TOK, 1024);
    copy_to_buf<<<dim3(8, 4), 256>>>(TOK, BUF, 0);
    sgemm2<<<dim3(48, 64), 256>>>(hidden, aiw, aib, QKVH, 8192, 3072, 1024);

    // Phase B: entire 31-step recurrence in one persistent kernel
    loop_kernel<<<128, 256>>>(aiw, aib, aow, aob, fw1, fb1, fw2, fb2,
                              ln1g, ln1b, ln2g, ln2b, QKVH,
                              TOK, Q, KVB, AO, TMP, H1, BUF);

    // Phase C
    comp_kernel<<<64, 256>>>(cq, BUF, SSUM);
    sgemm2<<<dim3(16, 1), 256>>>(SSUM, cw, cb, SUMM, 64, 1024, 1024);
    sgemm2<<<dim3(32, 1), 256>>>(SUMM, aiw + LL 1024 * 1024, aib + 1024, KVS, 64, 2048, 1024);
    final_attn<<<16384, 256>>>(QKVH, KVS, O);
    sgemm2<<<dim3(16, 64), 256>>>(O, aow, aob, ATT, 8192, 1024, 1024);
    ln_big<<<8192, 256>>>(hidden, ATT, ln1g, ln1b, out);
}

// round 8
// speedup vs baseline: 1.0418x; 1.0418x over previous
#include <cuda_runtime.h>

// ThoughtEngine: B=8, L=1024, D=1024, H=16, HD=64, S=32, C=8. fp32.
// R8: multi-launch loop (R5 topology) with LN fused into consumers (5 kernels
// per step), plus fixed FFMA2 GEMM (M-paired accumulators, B duplicated).

#define LL (size_t)

static const size_t OFF_QKVH = 0;                              // 8192*3072
static const size_t OFF_BUF  = OFF_QKVH + LL 8192 * 3072;      // 8*32*1024
static const size_t OFF_KVB  = OFF_BUF  + LL 8 * 32 * 1024;    // 8*32*2048
static const size_t OFF_CTX  = OFF_KVB  + LL 8 * 32 * 2048;
static const size_t OFF_TOK  = OFF_CTX + 8192;
static const size_t OFF_TMP  = OFF_TOK + 8192;
static const size_t OFF_TMP2 = OFF_TMP + 8192;
static const size_t OFF_TOKL = OFF_TMP2 + 8192;
static const size_t OFF_H1   = OFF_TOKL + 8192;                // 8*2048
static const size_t OFF_Q    = OFF_H1 + 16384;
static const size_t OFF_AO   = OFF_Q + 8192;
static const size_t OFF_KVS  = OFF_AO + 8192;                  // 64*2048
static const size_t OFF_SSUM = OFF_KVS + 131072;               // 64*1024
static const size_t OFF_O    = OFF_SSUM + 65536;               // 8192*1024
static const size_t OFF_ATT  = OFF_O + LL 8192 * 1024;         // 8192*1024
static const size_t SCR_TOT  = OFF_ATT + LL 8192 * 1024;

__device__ __align__(16) float g_scratch[SCR_TOT];

__device__ __forceinline__ float geluf(float x) {
    return 0.5f * x * (1.0f + erff(x * 0.7071067811865475f));
}

// In-place LayerNorm of 8 rows x 1024 staged in smem. blockDim == 256.
// Deterministic (same order in every block). st[] is 16 floats of smem.
__device__ __forceinline__ void ln_inplace(float* sA, const float* g,
                                           const float* bv, float* st) {
    int tid = threadIdx.x, lane = tid & 31, w = tid >> 5;   // 8 warps = 8 rows
    float s = 0.f;
    #pragma unroll
    for (int c = lane; c < 1024; c += 32) s += sA[w * 1024 + c];
    #pragma unroll
    for (int o = 16; o; o >>= 1) s += __shfl_xor_sync(0xffffffffu, s, o);
    float mean = s * (1.0f / 1024.0f);
    float v = 0.f;
    #pragma unroll
    for (int c = lane; c < 1024; c += 32) { float d = sA[w * 1024 + c] - mean; v += d * d; }
    #pragma unroll
    for (int o = 16; o; o >>= 1) v += __shfl_xor_sync(0xffffffffu, v, o);
    if (lane == 0) { st[w] = mean; st[8 + w] = rsqrtf(v * (1.0f / 1024.0f) + 1e-5f); }
    __syncthreads();
    for (int idx = tid; idx < 8192; idx += 256) {
        int r = idx >> 10, d = idx & 1023;
        sA[idx] = (sA[idx] - st[r]) * st[8 + r] * g[d] + bv[d];
    }
    __syncthreads();
}

// ctx[b,d] = mean_l hidden[b,l,d]
__global__ void mean_kernel(const float* __restrict__ hidden, float* __restrict__ ctx) {
    int b = blockIdx.y;
    int d = blockIdx.x * 256 + threadIdx.x;
    const float* p = hidden + LL b * 1048576 + d;
    float s = 0.f;
    #pragma unroll 8
    for (int l = 0; l < 1024; ++l) s += p[LL l * 1024];
    ctx[b * 1024 + d] = s * (1.0f / 1024.0f);
}

__global__ void copy_to_buf(const float* __restrict__ tok, float* __restrict__ buf, int slot) {
    int b = blockIdx.x;
    int d = blockIdx.y * 256 + threadIdx.x;
    buf[LL(b * 32 + slot) * 1024 + d] = tok[b * 1024 + d];
}

// ============================================================================
// FFMA2 GEMM v2: C[M,N] = A[M,K]@B[N,K]^T + bias. BM=128 BN=64 BK=16, 256 thr.
// Accumulator pairs along M (A pairs natural in smem); B duplicated so
// ld.shared.b64 yields (b,b). 16 fma.rn.f32x2 per k per thread, 64B LDS per k.
// ============================================================================
__global__ __launch_bounds__(256) void sgemm2(
    const float* __restrict__ A, const float* __restrict__ B,
    const float* __restrict__ bias, float* __restrict__ C,
    int M, int N, int K)
{
    __shared__ __align__(16) float As[16][128];
    __shared__ __align__(16) float Bs2[16][128];   // duplicated along N
    int tid = threadIdx.x;
    int tx = tid & 15, ty = tid >> 4;
    int bm = blockIdx.y * 128, bn = blockIdx.x * 64;
    unsigned long long acc2[4][4];
    #pragma unroll
    for (int p = 0; p < 4; ++p)
        #pragma unroll
        for (int j = 0; j < 4; ++j) acc2[p][j] = 0ull;

    for (int kk = 0; kk < K; kk += 16) {
        #pragma unroll
        for (int s = tid; s < 512; s += 256) {     // A: 128 rows x 4 float4
            int r = s >> 2, c = (s & 3) << 2;
            int gr = bm + r;
            float4 v = make_float4(0.f, 0.f, 0.f, 0.f);
            if (gr < M) v = *reinterpret_cast<const float4*>(A + LL gr * K + kk + c);
            As[c][r] = v.x; As[c + 1][r] = v.y; As[c + 2][r] = v.z; As[c + 3][r] = v.w;
        }
        {
            int r = tid >> 2, c = (tid & 3) << 2;  // B: 64 rows x 4 float4, duplicated
            float4 v = *reinterpret_cast<const float4*>(B + LL(bn + r) * K + kk + c);
            Bs2[c][2 * r] = v.x;     Bs2[c][2 * r + 1] = v.x;
            Bs2[c + 1][2 * r] = v.y; Bs2[c + 1][2 * r + 1] = v.y;
            Bs2[c + 2][2 * r] = v.z; Bs2[c + 2][2 * r + 1] = v.z;
            Bs2[c + 3][2 * r] = v.w; Bs2[c + 3][2 * r + 1] = v.w;
        }
        __syncthreads();
        #pragma unroll
        for (int k = 0; k < 16; ++k) {
            unsigned long long a2[4], b2[4];
            const unsigned long long* ap =
                reinterpret_cast<const unsigned long long*>(&As[k][0]) + ty * 4;
            #pragma unroll
            for (int p = 0; p < 4; ++p) a2[p] = ap[p];
            const unsigned long long* bp =
                reinterpret_cast<const unsigned long long*>(&Bs2[k][0]) + tx * 4;
            #pragma unroll
            for (int j = 0; j < 4; ++j) b2[j] = bp[j];
            #pragma unroll
            for (int p = 0; p < 4; ++p)
                #pragma unroll
                for (int j = 0; j < 4; ++j)
                    asm("fma.rn.f32x2 %0, %1, %2, %0;"
                        : "+l"(acc2[p][j]) : "l"(a2[p]), "l"(b2[j]));
        }
        __syncthreads();
    }
    #pragma unroll
    for (int p = 0; p < 4; ++p) {
        int row0 = bm + ty * 8 + 2 * p;
        #pragma unroll
        for (int j = 0; j < 4; ++j) {
            int col = bn + tx * 4 + j;
            unsigned long long v = acc2[p][j];
            float lo = __uint_as_float((unsigned)v);
            float hi = __uint_as_float((unsigned)(v >> 32));
            float bb = bias[col];
            if (row0 < M)     C[LL row0 * N + col] = lo + bb;
            if (row0 + 1 < M) C[LL(row0 + 1) * N + col] = hi + bb;
        }
    }
}

// out[b,n] = A[b,:K].W[n,:K] + bias[n], 8 rows, warp per n (Phase A tok0 only).
__global__ __launch_bounds__(256) void smallgemm8(
    const float* __restrict__ A, int K,
    const float* __restrict__ W, const float* __restrict__ bias,
    float* __restrict__ out, int N)
{
    __shared__ __align__(16) float As[8192];
    int tid = threadIdx.x, lane = tid & 31, w = tid >> 5;
    int n = blockIdx.x * 8 + w;
    float acc[8];
    #pragma unroll
    for (int b = 0; b < 8; ++b) acc[b] = 0.f;
    for (int kk = 0; kk < K; kk += 1024) {
        for (int i = tid; i < 8192; i += 256) {
            int b = i >> 10, k = i & 1023;
            As[i] = A[LL b * K + kk + k];
        }
        __syncthreads();
        const float4* wr = reinterpret_cast<const float4*>(W + LL n * K + kk);
        for (int k4 = lane; k4 < 256; k4 += 32) {
            float4 wv = wr[k4];
            #pragma unroll
            for (int b = 0; b < 8; ++b) {
                float4 av = reinterpret_cast<const float4*>(As + b * 1024)[k4];
                acc[b] += wv.x * av.x + wv.y * av.y + wv.z * av.z + wv.w * av.w;
            }
        }
        __syncthreads();
    }
    #pragma unroll
    for (int off = 16; off; off >>= 1)
        #pragma unroll
        for (int b = 0; b < 8; ++b) acc[b] += __shfl_down_sync(0xffffffffu, acc[b], off);
    if (lane == 0) {
        float bv = bias[n];
        #pragma unroll
        for (int b = 0; b < 8; ++b) out[b * N + n] = acc[b] + bv;
    }
}

// ============================================================================
// Loop kernels (5 per step)
// ============================================================================

// K0: (optional LN2 of pre) -> qkv. n<1024 -> q; else kvb slot step-1.
// When do_ln: bid 0 also publishes tok (LN2 result) and buf[:, step-1].
__global__ __launch_bounds__(256) void qkv_ln(
    const float* __restrict__ pre, float* tok,
    const float* __restrict__ aiw, const float* __restrict__ aib,
    const float* __restrict__ g2, const float* __restrict__ b2v,
    float* __restrict__ q, float* __restrict__ kvb, float* __restrict__ buf,
    int step, int do_ln)
{
    __shared__ __align__(16) float sA[8192];
    __shared__ float st[16];
    int tid = threadIdx.x, lane = tid & 31, w = tid >> 5;
    int bid = blockIdx.x;
    const float* src = do_ln ? pre : tok;
    for (int i = tid; i < 8192; i += 256) sA[i] = src[i];
    __syncthreads();
    if (do_ln) {
        ln_inplace(sA, g2, b2v, st);
        if (bid == 0) {
            for (int i = tid; i < 8192; i += 256) {
                tok[i] = sA[i];
                int b = i >> 10, d = i & 1023;
                buf[LL(b * 32 + step - 1) * 1024 + d] = sA[i];
            }
        }
    }
    int n = bid * 8 + w;   // 384 blocks -> n in [0,3072)
    const float4* wr = reinterpret_cast<const float4*>(aiw + LL n * 1024);
    float acc[8];
    #pragma unroll
    for (int b = 0; b < 8; ++b) acc[b] = 0.f;
    for (int k4 = lane; k4 < 256; k4 += 32) {
        float4 wv = wr[k4];
        #pragma unroll
        for (int b = 0; b < 8; ++b) {
            float4 av = reinterpret_cast<const float4*>(sA + b * 1024)[k4];
            acc[b] += wv.x * av.x + wv.y * av.y + wv.z * av.z + wv.w * av.w;
        }
    }
    #pragma unroll
    for (int off = 16; off; off >>= 1)
        #pragma unroll
        for (int b = 0; b < 8; ++b) acc[b] += __shfl_down_sync(0xffffffffu, acc[b], off);
    if (lane == 0) {
        float bv = aib[n];
        #pragma unroll
        for (int b = 0; b < 8; ++b) {
            float v = acc[b] + bv;
            if (n < 1024) q[b * 1024 + n] = v;
            else kvb[LL(b * 32 + step - 1) * 2048 + (n - 1024)] = v;
        }
    }
}

// K1: attention, block = (b,h), Lk = 1024 + step keys.
__global__ __launch_bounds__(256) void attn_step(
    const float* __restrict__ q, const float* __restrict__ qkvh,
    const float* __restrict__ kvb, float* __restrict__ ao, int Lk)
{
    int b = blockIdx.x >> 4, h = blockIdx.x & 15;
    __shared__ __align__(16) float sq[64];
    __shared__ float sc[1056];
    __shared__ float red[256];
    __shared__ float part[4][64];
    int tid = threadIdx.x;
    if (tid < 64) sq[tid] = q[b * 1024 + h * 64 + tid];
    __syncthreads();

    float lmax = -1e30f;
    for (int j = tid; j < Lk; j += 256) {
        const float* kr = (j < 1024)
            ? qkvh + LL(b * 1024 + j) * 3072 + 1024 + h * 64
            : kvb + LL(b * 32 + j - 1024) * 2048 + h * 64;
        const float4* k4 = reinterpret_cast<const float4*>(kr);
        const float4* q4 = reinterpret_cast<const float4*>(sq);
        float s = 0.f;
        #pragma unroll
        for (int d = 0; d < 16; ++d) {
            float4 kv = k4[d], qv = q4[d];
            s += kv.x * qv.x + kv.y * qv.y + kv.z * qv.z + kv.w * qv.w;
        }
        s *= 0.125f;
        sc[j] = s;
        lmax = fmaxf(lmax, s);
    }
    red[tid] = lmax; __syncthreads();
    for (int o = 128; o; o >>= 1) { if (tid < o) red[tid] = fmaxf(red[tid], red[tid + o]); __syncthreads(); }
    float m = red[0];
    __syncthreads();

    float lsum = 0.f;
    for (int j = tid; j < Lk; j += 256) { float p = __expf(sc[j] - m); sc[j] = p; lsum += p; }
    red[tid] = lsum; __syncthreads();
    for (int o = 128; o; o >>= 1) { if (tid < o) red[tid] += red[tid + o]; __syncthreads(); }
    float inv = 1.0f / red[0];

    int d = tid & 63, g = tid >> 6;
    float acc = 0.f;
    for (int j = g; j < Lk; j += 4) {
        const float* vr = (j < 1024)
            ? qkvh + LL(b * 1024 + j) * 3072 + 2048 + h * 64
            : kvb + LL(b * 32 + j - 1024) * 2048 + 1024 + h * 64;
        acc += sc[j] * vr[d];
    }
    part[g][d] = acc; __syncthreads();
    if (tid < 64)
        ao[b * 1024 + h * 64 + tid] =
            (part[0][tid] + part[1][tid] + part[2][tid] + part[3][tid]) * inv;
}

// K2: tmp = ao @ aow^T + aob + tok (residual). 128 blocks.
__global__ __launch_bounds__(256) void outproj_res(
    const float* __restrict__ ao, const float* __restrict__ aow,
    const float* __restrict__ aob, const float* __restrict__ tok,
    float* __restrict__ tmp)
{
    __shared__ __align__(16) float sA[8192];
    int tid = threadIdx.x, lane = tid & 31, w = tid >> 5;
    for (int i = tid; i < 8192; i += 256) sA[i] = ao[i];
    __syncthreads();
    int n = blockIdx.x * 8 + w;
    const float4* wr = reinterpret_cast<const float4*>(aow + LL n * 1024);
    float acc[8];
    #pragma unroll
    for (int b = 0; b < 8; ++b) acc[b] = 0.f;
    for (int k4 = lane; k4 < 256; k4 += 32) {
        float4 wv = wr[k4];
        #pragma unroll
        for (int b = 0; b < 8; ++b) {
            float4 av = reinterpret_cast<const float4*>(sA + b * 1024)[k4];
            acc[b] += wv.x * av.x + wv.y * av.y + wv.z * av.z + wv.w * av.w;
        }
    }
    #pragma unroll
    for (int off = 16; off; off >>= 1)
        #pragma unroll
        for (int b = 0; b < 8; ++b) acc[b] += __shfl_down_sync(0xffffffffu, acc[b], off);
    if (lane == 0) {
        float bv = aob[n];
        #pragma unroll
        for (int b = 0; b < 8; ++b)
            tmp[b * 1024 + n] = acc[b] + bv + tok[b * 1024 + n];
    }
}

// K3: LN1(tmp) in-block -> FFN1 + gelu -> h1. bid 0 publishes tokl = LN1(tmp).
__global__ __launch_bounds__(256) void ffn1_ln(
    const float* __restrict__ tmp,
    const float* __restrict__ g1, const float* __restrict__ b1v,
    const float* __restrict__ fw1, const float* __restrict__ fb1,
    float* __restrict__ h1, float* __restrict__ tokl)
{
    __shared__ __align__(16) float sA[8192];
    __shared__ float st[16];
    int tid = threadIdx.x, lane = tid & 31, w = tid >> 5;
    int bid = blockIdx.x;
    for (int i = tid; i < 8192; i += 256) sA[i] = tmp[i];
    __syncthreads();
    ln_inplace(sA, g1, b1v, st);
    if (bid == 0)
        for (int i = tid; i < 8192; i += 256) tokl[i] = sA[i];
    int n = bid * 8 + w;   // 256 blocks -> n in [0,2048)
    const float4* wr = reinterpret_cast<const float4*>(fw1 + LL n * 1024);
    float acc[8];
    #pragma unroll
    for (int b = 0; b < 8; ++b) acc[b] = 0.f;
    for (int k4 = lane; k4 < 256; k4 += 32) {
        float4 wv = wr[k4];
        #pragma unroll
        for (int b = 0; b < 8; ++b) {
            float4 av = reinterpret_cast<const float4*>(sA + b * 1024)[k4];
            acc[b] += wv.x * av.x + wv.y * av.y + wv.z * av.z + wv.w * av.w;
        }
    }
    #pragma unroll
    for (int off = 16; off; off >>= 1)
        #pragma unroll
        for (int b = 0; b < 8; ++b) acc[b] += __shfl_down_sync(0xffffffffu, acc[b], off);
    if (lane == 0) {
        float bv = fb1[n];
        #pragma unroll
        for (int b = 0; b < 8; ++b) h1[b * 2048 + n] = geluf(acc[b] + bv);
    }
}

// K4: tmp2 = h1 @ fw2^T + fb2 + tokl (residual). 128 blocks.
__global__ __launch_bounds__(256) void ffn2_res(
    const float* __restrict__ h1, const float* __restrict__ fw2,
    const float* __restrict__ fb2, const float* __restrict__ tokl,
    float* __restrict__ tmp2)
{
    __shared__ __align__(16) float sA[8192];
    int tid = threadIdx.x, lane = tid & 31, w = tid >> 5;
    int n = blockIdx.x * 8 + w;
    float acc[8];
    #pragma unroll
    for (int b = 0; b < 8; ++b) acc[b] = 0.f;
    for (int kk = 0; kk < 2048; kk += 1024) {
        for (int i = tid; i < 8192; i += 256) {
            int b = i >> 10, k = i & 1023;
            sA[i] = h1[b * 2048 + kk + k];
        }
        __syncthreads();
        const float4* wr = reinterpret_cast<const float4*>(fw2 + LL n * 2048 + kk);
        for (int k4 = lane; k4 < 256; k4 += 32) {
            float4 wv = wr[k4];
            #pragma unroll
            for (int b = 0; b < 8; ++b) {
                float4 av = reinterpret_cast<const float4*>(sA + b * 1024)[k4];
                acc[b] += wv.x * av.x + wv.y * av.y + wv.z * av.z + wv.w * av.w;
            }
        }
        __syncthreads();
    }
    #pragma unroll
    for (int off = 16; off; off >>= 1)
        #pragma unroll
        for (int b = 0; b < 8; ++b) acc[b] += __shfl_down_sync(0xffffffffu, acc[b], off);
    if (lane == 0) {
        float bv = fb2[n];
        #pragma unroll
        for (int b = 0; b < 8; ++b)
            tmp2[b * 1024 + n] = acc[b] + bv + tokl[b * 1024 + n];
    }
}

// Standalone LN of 8 rows (final step's LN2 -> buf slot 31).
__global__ void ln8(const float* __restrict__ x, const float* __restrict__ gg,
                    const float* __restrict__ bb, float* __restrict__ out,
                    float* __restrict__ buf, int slot)
{
    int b = blockIdx.x, tid = threadIdx.x;
    __shared__ float red[256];
    const float* xr = x + b * 1024;
    float vals[4]; float s = 0.f;
    #pragma unroll
    for (int i = 0; i < 4; ++i) { vals[i] = xr[tid + 256 * i]; s += vals[i]; }
    red[tid] = s; __syncthreads();
    for (int o = 128; o; o >>= 1) { if (tid < o) red[tid] += red[tid + o]; __syncthreads(); }
    float mean = red[0] * (1.0f / 1024.0f);
    __syncthreads();
    float v = 0.f;
    #pragma unroll
    for (int i = 0; i < 4; ++i) { float dd = vals[i] - mean; v += dd * dd; }
    red[tid] = v; __syncthreads();
    for (int o = 128; o; o >>= 1) { if (tid < o) red[tid] += red[tid + o]; __syncthreads(); }
    float inv = rsqrtf(red[0] * (1.0f / 1024.0f) + 1e-5f);
    #pragma unroll
    for (int i = 0; i < 4; ++i) {
        int d = tid + 256 * i;
        float y = (vals[i] - mean) * inv * gg[d] + bb[d];
        out[b * 1024 + d] = y;
        if (buf) buf[LL(b * 32 + slot) * 1024 + d] = y;
    }
}

// cond[l] = LN(hidden[l] + att[l])
__global__ void ln_big(const float* __restrict__ hidden, const float* __restrict__ att,
                       const float* __restrict__ gg, const float* __restrict__ bb,
                       float* __restrict__ out)
{
    int l = blockIdx.x, tid = threadIdx.x;
    __shared__ float red[256];
    const float* hr = hidden + LL l * 1024;
    const float* ar = att + LL l * 1024;
    float vals[4]; float s = 0.f;
    #pragma unroll
    for (int i = 0; i < 4; ++i) { vals[i] = hr[tid + 256 * i] + ar[tid + 256 * i]; s += vals[i]; }
    red[tid] = s; __syncthreads();
    for (int o = 128; o; o >>= 1) { if (tid < o) red[tid] += red[tid + o]; __syncthreads(); }
    float mean = red[0] * (1.0f / 1024.0f);
    __syncthreads();
    float v = 0.f;
    #pragma unroll
    for (int i = 0; i < 4; ++i) { float dd = vals[i] - mean; v += dd * dd; }
    red[tid] = v; __syncthreads();
    for (int o = 128; o; o >>= 1) { if (tid < o) red[tid] += red[tid + o]; __syncthreads(); }
    float inv = rsqrtf(red[0] * (1.0f / 1024.0f) + 1e-5f);
    #pragma unroll
    for (int i = 0; i < 4; ++i) {
        int d = tid + 256 * i;
        out[LL l * 1024 + d] = (vals[i] - mean) * inv * gg[d] + bb[d];
    }
}

// ssum[b,c,:] = softmax_s(comp_q[c].thoughts[b,s] / 32) @ thoughts[b]
__global__ __launch_bounds__(256) void comp_kernel(
    const float* __restrict__ comp_q, const float* __restrict__ thoughts,
    float* __restrict__ ssum)
{
    int b = blockIdx.x >> 3, c = blockIdx.x & 7;
    __shared__ float sc[32];
    __shared__ float pr[32];
    int tid = threadIdx.x, lane = tid & 31, w = tid >> 5;
    const float* qr = comp_q + c * 1024;
    #pragma unroll
    for (int si = 0; si < 4; ++si) {
        int s = w * 4 + si;
        const float* t = thoughts + LL(b * 32 + s) * 1024;
        float acc = 0.f;
        for (int k = lane; k < 1024; k += 32) acc += qr[k] * t[k];
        #pragma unroll
        for (int o = 16; o; o >>= 1) acc += __shfl_down_sync(0xffffffffu, acc, o);
        if (lane == 0) sc[s] = acc * (1.0f / 32.0f);
    }
    __syncthreads();
    if (tid == 0) {
        float m = -1e30f;
        for (int s = 0; s < 32; ++s) m = fmaxf(m, sc[s]);
        float S = 0.f;
        for (int s = 0; s < 32; ++s) { float p = __expf(sc[s] - m); pr[s] = p; S += p; }
        float iv = 1.0f / S;
        for (int s = 0; s < 32; ++s) pr[s] *= iv;
    }
    __syncthreads();
    for (int d = tid; d < 1024; d += 256) {
        float acc = 0.f;
        #pragma unroll
        for (int s = 0; s < 32; ++s) acc += pr[s] * thoughts[LL(b * 32 + s) * 1024 + d];
        ssum[LL(b * 8 + c) * 1024 + d] = acc;
    }
}

// Final MHA: one warp per (row l, head h); 8 keys from kvs (k|v rows).
__global__ __launch_bounds__(256) void final_attn(
    const float* __restrict__ qkvh, const float* __restrict__ kvs,
    float* __restrict__ o)
{
    int tid = threadIdx.x, lane = tid & 31, w = tid >> 5;
    int pair = blockIdx.x * 8 + w;
    int l = pair >> 4, h = pair & 15;
    int b = l >> 10;
    float2 qv = reinterpret_cast<const float2*>(qkvh + LL l * 3072 + h * 64)[lane];
    float s[8];
    #pragma unroll
    for (int ks = 0; ks < 8; ++ks) {
        float2 kv = reinterpret_cast<const float2*>(kvs + LL(b * 8 + ks) * 2048 + h * 64)[lane];
        float p = qv.x * kv.x + qv.y * kv.y;
        #pragma unroll
        for (int off = 16; off; off >>= 1) p += __shfl_xor_sync(0xffffffffu, p, off);
        s[ks] = p * 0.125f;
    }
    float m = s[0];
    #pragma unroll
    for (int ks = 1; ks < 8; ++ks) m = fmaxf(m, s[ks]);
    float sum = 0.f;
    #pragma unroll
    for (int ks = 0; ks < 8; ++ks) { s[ks] = __expf(s[ks] - m); sum += s[ks]; }
    float inv = 1.0f / sum;
    float o0 = 0.f, o1 = 0.f;
    #pragma unroll
    for (int ks = 0; ks < 8; ++ks) {
        float2 vv = reinterpret_cast<const float2*>(kvs + LL(b * 8 + ks) * 2048 + 1024 + h * 64)[lane];
        o0 += s[ks] * vv.x; o1 += s[ks] * vv.y;
    }
    float2 ov; ov.x = o0 * inv; ov.y = o1 * inv;
    reinterpret_cast<float2*>(o + LL l * 1024 + h * 64)[lane] = ov;
}

extern "C" void kernel_launch(void* const* d_in, const int* in_sizes, int n_in,
                              void* d_out, int out_size) {
    (void)in_sizes; (void)n_in; (void)out_size;
    const float* hidden = (const float*)d_in[0];
    const float* tpw    = (const float*)d_in[1];
    const float* tpb    = (const float*)d_in[2];
    const float* ln1g   = (const float*)d_in[3];
    const float* ln1b   = (const float*)d_in[4];
    const float* ln2g   = (const float*)d_in[5];
    const float* ln2b   = (const float*)d_in[6];
    const float* aiw    = (const float*)d_in[7];
    const float* aib    = (const float*)d_in[8];
    const float* aow    = (const float*)d_in[9];
    const float* aob    = (const float*)d_in[10];
    const float* fw1    = (const float*)d_in[11];
    const float* fb1    = (const float*)d_in[12];
    const float* fw2    = (const float*)d_in[13];
    const float* fb2    = (const float*)d_in[14];
    const float* cq     = (const float*)d_in[15];
    const float* cw     = (const float*)d_in[16];
    const float* cb     = (const float*)d_in[17];
    float* out = (float*)d_out;

    float* S;
    cudaGetSymbolAddress((void**)&S, g_scratch);
    float* QKVH = S + OFF_QKVH;
    float* BUF  = S + OFF_BUF;
    float* KVB  = S + OFF_KVB;
    float* CTX  = S + OFF_CTX;
    float* TOK  = S + OFF_TOK;
    float* TMP  = S + OFF_TMP;
    float* TMP2 = S + OFF_TMP2;
    float* TOKL = S + OFF_TOKL;
    float* H1   = S + OFF_H1;
    float* Q    = S + OFF_Q;
    float* AO   = S + OFF_AO;
    float* KVS  = S + OFF_KVS;
    float* SSUM = S + OFF_SSUM;
    float* O    = S + OFF_O;
    float* ATT  = S + OFF_ATT;
    float* SUMM = out + LL 8192 * 1024;   // (8,8,1024) tail of output

    // Phase A
    mean_kernel<<<dim3(4, 8), 256>>>(hidden, CTX);
    smallgemm8<<<128, 256>>>(CTX, 1024, tpw, tpb, TOK, 1024);
    copy_to_buf<<<dim3(8, 4), 256>>>(TOK, BUF, 0);
    sgemm2<<<dim3(48, 64), 256>>>(hidden, aiw, aib, QKVH, 8192, 3072, 1024);

    // Phase B: 31 steps x 5 kernels (LN2 fused into next step's qkv,
    // LN1 fused into FFN1)
    for (int i = 1; i < 32; ++i) {
        qkv_ln<<<384, 256>>>(TMP2, TOK, aiw, aib, ln2g, ln2b, Q, KVB, BUF, i, i > 1);
        attn_step<<<128, 256>>>(Q, QKVH, KVB, AO, 1024 + i);
        outproj_res<<<128, 256>>>(AO, aow, aob, TOK, TMP);
        ffn1_ln<<<256, 256>>>(TMP, ln1g, ln1b, fw1, fb1, H1, TOKL);
        ffn2_res<<<128, 256>>>(H1, fw2, fb2, TOKL, TMP2);
    }
    // Final LN2 -> buf[:,31]
    ln8<<<8, 256>>>(TMP2, ln2g, ln2b, TOK, BUF, 31);

    // Phase C
    comp_kernel<<<64, 256>>>(cq, BUF, SSUM);
    sgemm2<<<dim3(16, 1), 256>>>(SSUM, cw, cb, SUMM, 64, 1024, 1024);
    sgemm2<<<dim3(32, 1), 256>>>(SUMM, aiw + LL 1024 * 1024, aib + 1024, KVS, 64, 2048, 1024);
    final_attn<<<16384, 256>>>(QKVH, KVS, O);
    sgemm2<<<dim3(16, 64), 256>>>(O, aow, aob, ATT, 8192, 1024, 1024);
    ln_big<<<8192, 256>>>(hidden, ATT, ln1g, ln1b, out);
}

// round 10
// speedup vs baseline: 1.4279x; 1.3706x over previous
#include <cuda_runtime.h>

// ThoughtEngine: B=8, L=1024, D=1024, H=16, HD=64, S=32, C=8. fp32.
// R10 = R9 resubmit (infra failure last round): scalar sgemm (R5-proven) +
// 5-kernel fused loop (R8-proven) + float2 V-phase in attn_step.

#define LL (size_t)

static const size_t OFF_QKVH = 0;                              // 8192*3072
static const size_t OFF_BUF  = OFF_QKVH + LL 8192 * 3072;      // 8*32*1024
static const size_t OFF_KVB  = OFF_BUF  + LL 8 * 32 * 1024;    // 8*32*2048
static const size_t OFF_CTX  = OFF_KVB  + LL 8 * 32 * 2048;
static const size_t OFF_TOK  = OFF_CTX + 8192;
static const size_t OFF_TMP  = OFF_TOK + 8192;
static const size_t OFF_TMP2 = OFF_TMP + 8192;
static const size_t OFF_TOKL = OFF_TMP2 + 8192;
static const size_t OFF_H1   = OFF_TOKL + 8192;                // 8*2048
static const size_t OFF_Q    = OFF_H1 + 16384;
static const size_t OFF_AO   = OFF_Q + 8192;
static const size_t OFF_KVS  = OFF_AO + 8192;                  // 64*2048
static const size_t OFF_SSUM = OFF_KVS + 131072;               // 64*1024
static const size_t OFF_O    = OFF_SSUM + 65536;               // 8192*1024
static const size_t OFF_ATT  = OFF_O + LL 8192 * 1024;         // 8192*1024
static const size_t SCR_TOT  = OFF_ATT + LL 8192 * 1024;

__device__ __align__(16) float g_scratch[SCR_TOT];

__device__ __forceinline__ float geluf(float x) {
    return 0.5f * x * (1.0f + erff(x * 0.7071067811865475f));
}

// In-place LayerNorm of 8 rows x 1024 staged in smem. blockDim == 256.
__device__ __forceinline__ void ln_inplace(float* sA, const float* g,
                                           const float* bv, float* st) {
    int tid = threadIdx.x, lane = tid & 31, w = tid >> 5;   // 8 warps = 8 rows
    float s = 0.f;
    #pragma unroll
    for (int c = lane; c < 1024; c += 32) s += sA[w * 1024 + c];
    #pragma unroll
    for (int o = 16; o; o >>= 1) s += __shfl_xor_sync(0xffffffffu, s, o);
    float mean = s * (1.0f / 1024.0f);
    float v = 0.f;
    #pragma unroll
    for (int c = lane; c < 1024; c += 32) { float d = sA[w * 1024 + c] - mean; v += d * d; }
    #pragma unroll
    for (int o = 16; o; o >>= 1) v += __shfl_xor_sync(0xffffffffu, v, o);
    if (lane == 0) { st[w] = mean; st[8 + w] = rsqrtf(v * (1.0f / 1024.0f) + 1e-5f); }
    __syncthreads();
    for (int idx = tid; idx < 8192; idx += 256) {
        int r = idx >> 10, d = idx & 1023;
        sA[idx] = (sA[idx] - st[r]) * st[8 + r] * g[d] + bv[d];
    }
    __syncthreads();
}

// ctx[b,d] = mean_l hidden[b,l,d]
__global__ void mean_kernel(const float* __restrict__ hidden, float* __restrict__ ctx) {
    int b = blockIdx.y;
    int d = blockIdx.x * 256 + threadIdx.x;
    const float* p = hidden + LL b * 1048576 + d;
    float s = 0.f;
    #pragma unroll 8
    for (int l = 0; l < 1024; ++l) s += p[LL l * 1024];
    ctx[b * 1024 + d] = s * (1.0f / 1024.0f);
}

__global__ void copy_to_buf(const float* __restrict__ tok, float* __restrict__ buf, int slot) {
    int b = blockIdx.x;
    int d = blockIdx.y * 256 + threadIdx.x;
    buf[LL(b * 32 + slot) * 1024 + d] = tok[b * 1024 + d];
}

// Scalar GEMM (R5-proven): C[M,N] = A[M,K]@B[N,K]^T + bias. BM=128 BN=64 BK=16.
__global__ __launch_bounds__(256) void sgemm(
    const float* __restrict__ A, const float* __restrict__ B,
    const float* __restrict__ bias, float* __restrict__ C,
    int M, int N, int K)
{
    __shared__ __align__(16) float As[16][128];
    __shared__ __align__(16) float Bs[16][64];
    int tid = threadIdx.x;
    int tx = tid & 15, ty = tid >> 4;
    int bm = blockIdx.y * 128, bn = blockIdx.x * 64;
    float acc[8][4];
    #pragma unroll
    for (int i = 0; i < 8; ++i)
        #pragma unroll
        for (int j = 0; j < 4; ++j) acc[i][j] = 0.f;

    for (int kk = 0; kk < K; kk += 16) {
        #pragma unroll
        for (int s = tid; s < 512; s += 256) {
            int r = s >> 2, c = (s & 3) << 2;
            int gr = bm + r;
            float4 v = make_float4(0.f, 0.f, 0.f, 0.f);
            if (gr < M) v = *reinterpret_cast<const float4*>(A + LL gr * K + kk + c);
            As[c][r] = v.x; As[c + 1][r] = v.y; As[c + 2][r] = v.z; As[c + 3][r] = v.w;
        }
        {
            int r = tid >> 2, c = (tid & 3) << 2;
            float4 v = *reinterpret_cast<const float4*>(B + LL(bn + r) * K + kk + c);
            Bs[c][r] = v.x; Bs[c + 1][r] = v.y; Bs[c + 2][r] = v.z; Bs[c + 3][r] = v.w;
        }
        __syncthreads();
        #pragma unroll
        for (int k = 0; k < 16; ++k) {
            float a[8], bb[4];
            #pragma unroll
            for (int i = 0; i < 8; ++i) a[i] = As[k][ty * 8 + i];
            #pragma unroll
            for (int j = 0; j < 4; ++j) bb[j] = Bs[k][tx * 4 + j];
            #pragma unroll
            for (int i = 0; i < 8; ++i)
                #pragma unroll
                for (int j = 0; j < 4; ++j) acc[i][j] += a[i] * bb[j];
        }
        __syncthreads();
    }
    #pragma unroll
    for (int i = 0; i < 8; ++i) {
        int row = bm + ty * 8 + i;
        if (row < M) {
            float* cr = C + LL row * N + bn + tx * 4;
            #pragma unroll
            for (int j = 0; j < 4; ++j) cr[j] = acc[i][j] + bias[bn + tx * 4 + j];
        }
    }
}

// out[b,n] = A[b,:K].W[n,:K] + bias[n], 8 rows, warp per n (Phase A tok0 only).
__global__ __launch_bounds__(256) void smallgemm8(
    const float* __restrict__ A, int K,
    const float* __restrict__ W, const float* __restrict__ bias,
    float* __restrict__ out, int N)
{
    __shared__ __align__(16) float As[8192];
    int tid = threadIdx.x, lane = tid & 31, w = tid >> 5;
    int n = blockIdx.x * 8 + w;
    float acc[8];
    #pragma unroll
    for (int b = 0; b < 8; ++b) acc[b] = 0.f;
    for (int kk = 0; kk < K; kk += 1024) {
        for (int i = tid; i < 8192; i += 256) {
            int b = i >> 10, k = i & 1023;
            As[i] = A[LL b * K + kk + k];
        }
        __syncthreads();
        const float4* wr = reinterpret_cast<const float4*>(W + LL n * K + kk);
        for (int k4 = lane; k4 < 256; k4 += 32) {
            float4 wv = wr[k4];
            #pragma unroll
            for (int b = 0; b < 8; ++b) {
                float4 av = reinterpret_cast<const float4*>(As + b * 1024)[k4];
                acc[b] += wv.x * av.x + wv.y * av.y + wv.z * av.z + wv.w * av.w;
            }
        }
        __syncthreads();
    }
    #pragma unroll
    for (int off = 16; off; off >>= 1)
        #pragma unroll
        for (int b = 0; b < 8; ++b) acc[b] += __shfl_down_sync(0xffffffffu, acc[b], off);
    if (lane == 0) {
        float bv = bias[n];
        #pragma unroll
        for (int b = 0; b < 8; ++b) out[b * N + n] = acc[b] + bv;
    }
}

// ============================================================================
// Loop kernels (5 per step)
// ============================================================================

// K0: (optional LN2 of pre) -> qkv. n<1024 -> q; else kvb slot step-1.
__global__ __launch_bounds__(256) void qkv_ln(
    const float* __restrict__ pre, float* tok,
    const float* __restrict__ aiw, const float* __restrict__ aib,
    const float* __restrict__ g2, const float* __restrict__ b2v,
    float* __restrict__ q, float* __restrict__ kvb, float* __restrict__ buf,
    int step, int do_ln)
{
    __shared__ __align__(16) float sA[8192];
    __shared__ float st[16];
    int tid = threadIdx.x, lane = tid & 31, w = tid >> 5;
    int bid = blockIdx.x;
    const float* src = do_ln ? pre : tok;
    for (int i = tid; i < 8192; i += 256) sA[i] = src[i];
    __syncthreads();
    if (do_ln) {
        ln_inplace(sA, g2, b2v, st);
        if (bid == 0) {
            for (int i = tid; i < 8192; i += 256) {
                tok[i] = sA[i];
                int b = i >> 10, d = i & 1023;
                buf[LL(b * 32 + step - 1) * 1024 + d] = sA[i];
            }
        }
    }
    int n = bid * 8 + w;   // 384 blocks -> n in [0,3072)
    const float4* wr = reinterpret_cast<const float4*>(aiw + LL n * 1024);
    float acc[8];
    #pragma unroll
    for (int b = 0; b < 8; ++b) acc[b] = 0.f;
    for (int k4 = lane; k4 < 256; k4 += 32) {
        float4 wv = wr[k4];
        #pragma unroll
        for (int b = 0; b < 8; ++b) {
            float4 av = reinterpret_cast<const float4*>(sA + b * 1024)[k4];
            acc[b] += wv.x * av.x + wv.y * av.y + wv.z * av.z + wv.w * av.w;
        }
    }
    #pragma unroll
    for (int off = 16; off; off >>= 1)
        #pragma unroll
        for (int b = 0; b < 8; ++b) acc[b] += __shfl_down_sync(0xffffffffu, acc[b], off);
    if (lane == 0) {
        float bv = aib[n];
        #pragma unroll
        for (int b = 0; b < 8; ++b) {
            float v = acc[b] + bv;
            if (n < 1024) q[b * 1024 + n] = v;
            else kvb[LL(b * 32 + step - 1) * 2048 + (n - 1024)] = v;
        }
    }
}

// K1: attention, block = (b,h), Lk = 1024 + step keys. float2 V-phase.
__global__ __launch_bounds__(256) void attn_step(
    const float* __restrict__ q, const float* __restrict__ qkvh,
    const float* __restrict__ kvb, float* __restrict__ ao, int Lk)
{
    int b = blockIdx.x >> 4, h = blockIdx.x & 15;
    __shared__ __align__(16) float sq[64];
    __shared__ float sc[1056];
    __shared__ float red[256];
    __shared__ float part[8][64];
    int tid = threadIdx.x;
    if (tid < 64) sq[tid] = q[b * 1024 + h * 64 + tid];
    __syncthreads();

    float lmax = -1e30f;
    for (int j = tid; j < Lk; j += 256) {
        const float* kr = (j < 1024)
            ? qkvh + LL(b * 1024 + j) * 3072 + 1024 + h * 64
            : kvb + LL(b * 32 + j - 1024) * 2048 + h * 64;
        const float4* k4 = reinterpret_cast<const float4*>(kr);
        const float4* q4 = reinterpret_cast<const float4*>(sq);
        float s = 0.f;
        #pragma unroll
        for (int d = 0; d < 16; ++d) {
            float4 kv = k4[d], qv = q4[d];
            s += kv.x * qv.x + kv.y * qv.y + kv.z * qv.z + kv.w * qv.w;
        }
        s *= 0.125f;
        sc[j] = s;
        lmax = fmaxf(lmax, s);
    }
    red[tid] = lmax; __syncthreads();
    for (int o = 128; o; o >>= 1) { if (tid < o) red[tid] = fmaxf(red[tid], red[tid + o]); __syncthreads(); }
    float m = red[0];
    __syncthreads();

    float lsum = 0.f;
    for (int j = tid; j < Lk; j += 256) { float p = __expf(sc[j] - m); sc[j] = p; lsum += p; }
    red[tid] = lsum; __syncthreads();
    for (int o = 128; o; o >>= 1) { if (tid < o) red[tid] += red[tid + o]; __syncthreads(); }
    float inv = 1.0f / red[0];

    // V-phase: 8 groups of 32 lanes, each thread accumulates 2 d-columns.
    int g = tid >> 5, d0 = (tid & 31) * 2;
    float ax = 0.f, ay = 0.f;
    for (int j = g; j < Lk; j += 8) {
        const float* vr = (j < 1024)
            ? qkvh + LL(b * 1024 + j) * 3072 + 2048 + h * 64
            : kvb + LL(b * 32 + j - 1024) * 2048 + 1024 + h * 64;
        float2 v = *reinterpret_cast<const float2*>(vr + d0);
        float p = sc[j];
        ax += p * v.x; ay += p * v.y;
    }
    part[g][d0] = ax; part[g][d0 + 1] = ay;
    __syncthreads();
    if (tid < 64) {
        float s = 0.f;
        #pragma unroll
        for (int gg = 0; gg < 8; ++gg) s += part[gg][tid];
        ao[b * 1024 + h * 64 + tid] = s * inv;
    }
}

// K2: tmp = ao @ aow^T + aob + tok (residual). 128 blocks.
__global__ __launch_bounds__(256) void outproj_res(
    const float* __restrict__ ao, const float* __restrict__ aow,
    const float* __restrict__ aob, const float* __restrict__ tok,
    float* __restrict__ tmp)
{
    __shared__ __align__(16) float sA[8192];
    int tid = threadIdx.x, lane = tid & 31, w = tid >> 5;
    for (int i = tid; i < 8192; i += 256) sA[i] = ao[i];
    __syncthreads();
    int n = blockIdx.x * 8 + w;
    const float4* wr = reinterpret_cast<const float4*>(aow + LL n * 1024);
    float acc[8];
    #pragma unroll
    for (int b = 0; b < 8; ++b) acc[b] = 0.f;
    for (int k4 = lane; k4 < 256; k4 += 32) {
        float4 wv = wr[k4];
        #pragma unroll
        for (int b = 0; b < 8; ++b) {
            float4 av = reinterpret_cast<const float4*>(sA + b * 1024)[k4];
            acc[b] += wv.x * av.x + wv.y * av.y + wv.z * av.z + wv.w * av.w;
        }
    }
    #pragma unroll
    for (int off = 16; off; off >>= 1)
        #pragma unroll
        for (int b = 0; b < 8; ++b) acc[b] += __shfl_down_sync(0xffffffffu, acc[b], off);
    if (lane == 0) {
        float bv = aob[n];
        #pragma unroll
        for (int b = 0; b < 8; ++b)
            tmp[b * 1024 + n] = acc[b] + bv + tok[b * 1024 + n];
    }
}

// K3: LN1(tmp) in-block -> FFN1 + gelu -> h1. bid 0 publishes tokl = LN1(tmp).
__global__ __launch_bounds__(256) void ffn1_ln(
    const float* __restrict__ tmp,
    const float* __restrict__ g1, const float* __restrict__ b1v,
    const float* __restrict__ fw1, const float* __restrict__ fb1,
    float* __restrict__ h1, float* __restrict__ tokl)
{
    __shared__ __align__(16) float sA[8192];
    __shared__ float st[16];
    int tid = threadIdx.x, lane = tid & 31, w = tid >> 5;
    int bid = blockIdx.x;
    for (int i = tid; i < 8192; i += 256) sA[i] = tmp[i];
    __syncthreads();
    ln_inplace(sA, g1, b1v, st);
    if (bid == 0)
        for (int i = tid; i < 8192; i += 256) tokl[i] = sA[i];
    int n = bid * 8 + w;   // 256 blocks -> n in [0,2048)
    const float4* wr = reinterpret_cast<const float4*>(fw1 + LL n * 1024);
    float acc[8];
    #pragma unroll
    for (int b = 0; b < 8; ++b) acc[b] = 0.f;
    for (int k4 = lane; k4 < 256; k4 += 32) {
        float4 wv = wr[k4];
        #pragma unroll
        for (int b = 0; b < 8; ++b) {
            float4 av = reinterpret_cast<const float4*>(sA + b * 1024)[k4];
            acc[b] += wv.x * av.x + wv.y * av.y + wv.z * av.z + wv.w * av.w;
        }
    }
    #pragma unroll
    for (int off = 16; off; off >>= 1)
        #pragma unroll
        for (int b = 0; b < 8; ++b) acc[b] += __shfl_down_sync(0xffffffffu, acc[b], off);
    if (lane == 0) {
        float bv = fb1[n];
        #pragma unroll
        for (int b = 0; b < 8; ++b) h1[b * 2048 + n] = geluf(acc[b] + bv);
    }
}

// K4: tmp2 = h1 @ fw2^T + fb2 + tokl (residual). 128 blocks.
__global__ __launch_bounds__(256) void ffn2_res(
    const float* __restrict__ h1, const float* __restrict__ fw2,
    const float* __restrict__ fb2, const float* __restrict__ tokl,
    float* __restrict__ tmp2)
{
    __shared__ __align__(16) float sA[8192];
    int tid = threadIdx.x, lane = tid & 31, w = tid >> 5;
    int n = blockIdx.x * 8 + w;
    float acc[8];
    #pragma unroll
    for (int b = 0; b < 8; ++b) acc[b] = 0.f;
    for (int kk = 0; kk < 2048; kk += 1024) {
        for (int i = tid; i < 8192; i += 256) {
            int b = i >> 10, k = i & 1023;
            sA[i] = h1[b * 2048 + kk + k];
        }
        __syncthreads();
        const float4* wr = reinterpret_cast<const float4*>(fw2 + LL n * 2048 + kk);
        for (int k4 = lane; k4 < 256; k4 += 32) {
            float4 wv = wr[k4];
            #pragma unroll
            for (int b = 0; b < 8; ++b) {
                float4 av = reinterpret_cast<const float4*>(sA + b * 1024)[k4];
                acc[b] += wv.x * av.x + wv.y * av.y + wv.z * av.z + wv.w * av.w;
            }
        }
        __syncthreads();
    }
    #pragma unroll
    for (int off = 16; off; off >>= 1)
        #pragma unroll
        for (int b = 0; b < 8; ++b) acc[b] += __shfl_down_sync(0xffffffffu, acc[b], off);
    if (lane == 0) {
        float bv = fb2[n];
        #pragma unroll
        for (int b = 0; b < 8; ++b)
            tmp2[b * 1024 + n] = acc[b] + bv + tokl[b * 1024 + n];
    }
}

// Standalone LN of 8 rows (final step's LN2 -> buf slot 31).
__global__ void ln8(const float* __restrict__ x, const float* __restrict__ gg,
                    const float* __restrict__ bb, float* __restrict__ out,
                    float* __restrict__ buf, int slot)
{
    int b = blockIdx.x, tid = threadIdx.x;
    __shared__ float red[256];
    const float* xr = x + b * 1024;
    float vals[4]; float s = 0.f;
    #pragma unroll
    for (int i = 0; i < 4; ++i) { vals[i] = xr[tid + 256 * i]; s += vals[i]; }
    red[tid] = s; __syncthreads();
    for (int o = 128; o; o >>= 1) { if (tid < o) red[tid] += red[tid + o]; __syncthreads(); }
    float mean = red[0] * (1.0f / 1024.0f);
    __syncthreads();
    float v = 0.f;
    #pragma unroll
    for (int i = 0; i < 4; ++i) { float dd = vals[i] - mean; v += dd * dd; }
    red[tid] = v; __syncthreads();
    for (int o = 128; o; o >>= 1) { if (tid < o) red[tid] += red[tid + o]; __syncthreads(); }
    float inv = rsqrtf(red[0] * (1.0f / 1024.0f) + 1e-5f);
    #pragma unroll
    for (int i = 0; i < 4; ++i) {
        int d = tid + 256 * i;
        float y = (vals[i] - mean) * inv * gg[d] + bb[d];
        out[b * 1024 + d] = y;
        if (buf) buf[LL(b * 32 + slot) * 1024 + d] = y;
    }
}

// cond[l] = LN(hidden[l] + att[l])
__global__ void ln_big(const float* __restrict__ hidden, const float* __restrict__ att,
                       const float* __restrict__ gg, const float* __restrict__ bb,
                       float* __restrict__ out)
{
    int l = blockIdx.x, tid = threadIdx.x;
    __shared__ float red[256];
    const float* hr = hidden + LL l * 1024;
    const float* ar = att + LL l * 1024;
    float vals[4]; float s = 0.f;
    #pragma unroll
    for (int i = 0; i < 4; ++i) { vals[i] = hr[tid + 256 * i] + ar[tid + 256 * i]; s += vals[i]; }
    red[tid] = s; __syncthreads();
    for (int o = 128; o; o >>= 1) { if (tid < o) red[tid] += red[tid + o]; __syncthreads(); }
    float mean = red[0] * (1.0f / 1024.0f);
    __syncthreads();
    float v = 0.f;
    #pragma unroll
    for (int i = 0; i < 4; ++i) { float dd = vals[i] - mean; v += dd * dd; }
    red[tid] = v; __syncthreads();
    for (int o = 128; o; o >>= 1) { if (tid < o) red[tid] += red[tid + o]; __syncthreads(); }
    float inv = rsqrtf(red[0] * (1.0f / 1024.0f) + 1e-5f);
    #pragma unroll
    for (int i = 0; i < 4; ++i) {
        int d = tid + 256 * i;
        out[LL l * 1024 + d] = (vals[i] - mean) * inv * gg[d] + bb[d];
    }
}

// ssum[b,c,:] = softmax_s(comp_q[c].thoughts[b,s] / 32) @ thoughts[b]
__global__ __launch_bounds__(256) void comp_kernel(
    const float* __restrict__ comp_q, const float* __restrict__ thoughts,
    float* __restrict__ ssum)
{
    int b = blockIdx.x >> 3, c = blockIdx.x & 7;
    __shared__ float sc[32];
    __shared__ float pr[32];
    int tid = threadIdx.x, lane = tid & 31, w = tid >> 5;
    const float* qr = comp_q + c * 1024;
    #pragma unroll
    for (int si = 0; si < 4; ++si) {
        int s = w * 4 + si;
        const float* t = thoughts + LL(b * 32 + s) * 1024;
        float acc = 0.f;
        for (int k = lane; k < 1024; k += 32) acc += qr[k] * t[k];
        #pragma unroll
        for (int o = 16; o; o >>= 1) acc += __shfl_down_sync(0xffffffffu, acc, o);
        if (lane == 0) sc[s] = acc * (1.0f / 32.0f);
    }
    __syncthreads();
    if (tid == 0) {
        float m = -1e30f;
        for (int s = 0; s < 32; ++s) m = fmaxf(m, sc[s]);
        float S = 0.f;
        for (int s = 0; s < 32; ++s) { float p = __expf(sc[s] - m); pr[s] = p; S += p; }
        float iv = 1.0f / S;
        for (int s = 0; s < 32; ++s) pr[s] *= iv;
    }
    __syncthreads();
    for (int d = tid; d < 1024; d += 256) {
        float acc = 0.f;
        #pragma unroll
        for (int s = 0; s < 32; ++s) acc += pr[s] * thoughts[LL(b * 32 + s) * 1024 + d];
        ssum[LL(b * 8 + c) * 1024 + d] = acc;
    }
}

// Final MHA: one warp per (row l, head h); 8 keys from kvs (k|v rows).
__global__ __launch_bounds__(256) void final_attn(
    const float* __restrict__ qkvh, const float* __restrict__ kvs,
    float* __restrict__ o)
{
    int tid = threadIdx.x, lane = tid & 31, w = tid >> 5;
    int pair = blockIdx.x * 8 + w;
    int l = pair >> 4, h = pair & 15;
    int b = l >> 10;
    float2 qv = reinterpret_cast<const float2*>(qkvh + LL l * 3072 + h * 64)[lane];
    float s[8];
    #pragma unroll
    for (int ks = 0; ks < 8; ++ks) {
        float2 kv = reinterpret_cast<const float2*>(kvs + LL(b * 8 + ks) * 2048 + h * 64)[lane];
        float p = qv.x * kv.x + qv.y * kv.y;
        #pragma unroll
        for (int off = 16; off; off >>= 1) p += __shfl_xor_sync(0xffffffffu, p, off);
        s[ks] = p * 0.125f;
    }
    float m = s[0];
    #pragma unroll
    for (int ks = 1; ks < 8; ++ks) m = fmaxf(m, s[ks]);
    float sum = 0.f;
    #pragma unroll
    for (int ks = 0; ks < 8; ++ks) { s[ks] = __expf(s[ks] - m); sum += s[ks]; }
    float inv = 1.0f / sum;
    float o0 = 0.f, o1 = 0.f;
    #pragma unroll
    for (int ks = 0; ks < 8; ++ks) {
        float2 vv = reinterpret_cast<const float2*>(kvs + LL(b * 8 + ks) * 2048 + 1024 + h * 64)[lane];
        o0 += s[ks] * vv.x; o1 += s[ks] * vv.y;
    }
    float2 ov; ov.x = o0 * inv; ov.y = o1 * inv;
    reinterpret_cast<float2*>(o + LL l * 1024 + h * 64)[lane] = ov;
}

extern "C" void kernel_launch(void* const* d_in, const int* in_sizes, int n_in,
                              void* d_out, int out_size) {
    (void)in_sizes; (void)n_in; (void)out_size;
    const float* hidden = (const float*)d_in[0];
    const float* tpw    = (const float*)d_in[1];
    const float* tpb    = (const float*)d_in[2];
    const float* ln1g   = (const float*)d_in[3];
    const float* ln1b   = (const float*)d_in[4];
    const float* ln2g   = (const float*)d_in[5];
    const float* ln2b   = (const float*)d_in[6];
    const float* aiw    = (const float*)d_in[7];
    const float* aib    = (const float*)d_in[8];
    const float* aow    = (const float*)d_in[9];
    const float* aob    = (const float*)d_in[10];
    const float* fw1    = (const float*)d_in[11];
    const float* fb1    = (const float*)d_in[12];
    const float* fw2    = (const float*)d_in[13];
    const float* fb2    = (const float*)d_in[14];
    const float* cq     = (const float*)d_in[15];
    const float* cw     = (const float*)d_in[16];
    const float* cb     = (const float*)d_in[17];
    float* out = (float*)d_out;

    float* S;
    cudaGetSymbolAddress((void**)&S, g_scratch);
    float* QKVH = S + OFF_QKVH;
    float* BUF  = S + OFF_BUF;
    float* KVB  = S + OFF_KVB;
    float* CTX  = S + OFF_CTX;
    float* TOK  = S + OFF_TOK;
    float* TMP  = S + OFF_TMP;
    float* TMP2 = S + OFF_TMP2;
    float* TOKL = S + OFF_TOKL;
    float* H1   = S + OFF_H1;
    float* Q    = S + OFF_Q;
    float* AO   = S + OFF_AO;
    float* KVS  = S + OFF_KVS;
    float* SSUM = S + OFF_SSUM;
    float* O    = S + OFF_O;
    float* ATT  = S + OFF_ATT;
    float* SUMM = out + LL 8192 * 1024;   // (8,8,1024) tail of output

    // Phase A
    mean_kernel<<<dim3(4, 8), 256>>>(hidden, CTX);
    smallgemm8<<<128, 256>>>(CTX, 1024, tpw, tpb, TOK, 1024);
    copy_to_buf<<<dim3(8, 4), 256>>>(TOK, BUF, 0);
    sgemm<<<dim3(48, 64), 256>>>(hidden, aiw, aib, QKVH, 8192, 3072, 1024);

    // Phase B: 31 steps x 5 kernels
    for (int i = 1; i < 32; ++i) {
        qkv_ln<<<384, 256>>>(TMP2, TOK, aiw, aib, ln2g, ln2b, Q, KVB, BUF, i, i > 1);
        attn_step<<<128, 256>>>(Q, QKVH, KVB, AO, 1024 + i);
        outproj_res<<<128, 256>>>(AO, aow, aob, TOK, TMP);
        ffn1_ln<<<256, 256>>>(TMP, ln1g, ln1b, fw1, fb1, H1, TOKL);
        ffn2_res<<<128, 256>>>(H1, fw2, fb2, TOKL, TMP2);
    }
    // Final LN2 -> buf[:,31]
    ln8<<<8, 256>>>(TMP2, ln2g, ln2b, TOK, BUF, 31);

    // Phase C
    comp_kernel<<<64, 256>>>(cq, BUF, SSUM);
    sgemm<<<dim3(16, 1), 256>>>(SSUM, cw, cb, SUMM, 64, 1024, 1024);
    sgemm<<<dim3(32, 1), 256>>>(SUMM, aiw + LL 1024 * 1024, aib + 1024, KVS, 64, 2048, 1024);
    final_attn<<<16384, 256>>>(QKVH, KVS, O);
    sgemm<<<dim3(16, 64), 256>>>(O, aow, aob, ATT, 8192, 1024, 1024);
    ln_big<<<8192, 256>>>(hidden, ATT, ln1g, ln1b, out);
}